// round 1
// baseline (speedup 1.0000x reference)
#include <cuda_runtime.h>
#include <math.h>

#define B_SZ  16384
#define EMB   128
#define NF    4
#define D_IN  512
#define H1    2048
#define H2    1024
#define H3    512

// ---- scratch (device globals; no allocation allowed) ----
__device__ float g_embed[B_SZ * D_IN];   // 33.5 MB
__device__ float g_h1[B_SZ * H1];        // 134 MB
__device__ float g_h2[B_SZ * H2];        // 67 MB
__device__ float g_h3[B_SZ * H3];        // 33.5 MB
__device__ float g_fm0[B_SZ];            // bias + linear term per row
__device__ float g_t[B_SZ];              // per-row (sum^2 - sum_sq)
__device__ float g_S[1];                 // global scalar reduction

__constant__ int c_offsets[4] = {0, 31360, 38167, 38185};

// ---- packed f32x2 helpers (Blackwell sm_100+) ----
__device__ __forceinline__ unsigned long long pack2(float x, float y) {
    unsigned long long r;
    asm("mov.b64 %0, {%1, %2};" : "=l"(r) : "f"(x), "f"(y));
    return r;
}
__device__ __forceinline__ void unpack2(unsigned long long v, float& x, float& y) {
    asm("mov.b64 {%0, %1}, %2;" : "=f"(x), "=f"(y) : "l"(v));
}
__device__ __forceinline__ void ffma2(unsigned long long& c, unsigned long long a,
                                      unsigned long long b) {
    asm("fma.rn.f32x2 %0, %1, %2, %0;" : "+l"(c) : "l"(a), "l"(b));
}

// ============================================================================
// Kernel 1: embedding gather + FM partial terms
//   grid = B rows, 128 threads (one per EMB dim)
// ============================================================================
__global__ void gather_fm_kernel(const float* __restrict__ x,
                                 const float* __restrict__ bias,
                                 const float* __restrict__ fc,
                                 const float* __restrict__ emb) {
    const int row = blockIdx.x;
    const int d   = threadIdx.x;  // 0..127

    int idx[NF];
#pragma unroll
    for (int f = 0; f < NF; f++) idx[f] = (int)x[row * NF + f];

    float s = 0.f, ss = 0.f;
#pragma unroll
    for (int f = 0; f < NF; f++) {
        float e = emb[(long long)idx[f] * EMB + d];
        g_embed[(long long)row * D_IN + f * EMB + d] = e;
        s  += e;
        ss += e * e;
    }
    // reduce s and ss over all 128 threads (all 512 embed values of the row)
#pragma unroll
    for (int o = 16; o > 0; o >>= 1) {
        s  += __shfl_xor_sync(0xffffffff, s,  o);
        ss += __shfl_xor_sync(0xffffffff, ss, o);
    }
    __shared__ float ws[4], wss[4];
    if ((d & 31) == 0) { ws[d >> 5] = s; wss[d >> 5] = ss; }
    __syncthreads();
    if (d == 0) {
        float s_all  = ws[0] + ws[1] + ws[2] + ws[3];
        float ss_all = wss[0] + wss[1] + wss[2] + wss[3];
        g_t[row] = s_all * s_all - ss_all;
        float lin = 0.f;
#pragma unroll
        for (int f = 0; f < NF; f++) lin += fc[idx[f] + c_offsets[f]];
        g_fm0[row] = bias[0] + lin;
    }
}

// ============================================================================
// Kernel 2: deterministic global reduction of g_t -> g_S (scalar)
// ============================================================================
__global__ void reduce_t_kernel() {
    __shared__ float sm[1024];
    const int tid = threadIdx.x;
    float s = 0.f;
    for (int i = tid; i < B_SZ; i += 1024) s += g_t[i];
    sm[tid] = s;
    __syncthreads();
#pragma unroll
    for (int o = 512; o > 0; o >>= 1) {
        if (tid < o) sm[tid] += sm[tid + o];
        __syncthreads();
    }
    if (tid == 0) g_S[0] = sm[0];
}

// ============================================================================
// Kernel 3: tiled SGEMM with f32x2 packed FMAs, bias + optional ReLU epilogue
//   C[M,N] = act(A[M,K] @ W[K,N] + bias),  M=16384, N,K multiples of 128/16
//   BM=BN=128, BK=16, 256 threads, 8x8 per thread
// ============================================================================
#define BM 128
#define BN 128
#define BK 16
#define ASTRIDE 132   // padded to break STS bank conflicts

__global__ __launch_bounds__(256, 2) void sgemm_bias_act(
    const float* __restrict__ A, const float* __restrict__ W,
    const float* __restrict__ bias, float* __restrict__ C,
    int N, int K, int do_relu) {
    __shared__ float As[BK * ASTRIDE];  // transposed: As[k][m]
    __shared__ float Bs[BK * BN];       // Bs[k][n]

    const int tid = threadIdx.x;
    const int tx = tid & 15;   // col group (8 cols each)
    const int ty = tid >> 4;   // row group (8 rows each)
    const long long block_row = (long long)blockIdx.y * BM;
    const int block_col = blockIdx.x * BN;

    // A tile loads: 128x16 floats = 512 float4, 2 per thread
    const int a_r = tid >> 2;         // 0..63
    const int a_c = (tid & 3) << 2;   // 0,4,8,12
    // B tile loads: 16x128 floats = 512 float4, 2 per thread
    const int b_r = tid >> 5;         // 0..7
    const int b_c = (tid & 31) << 2;  // 0..124

    unsigned long long acc[8][4];
#pragma unroll
    for (int m = 0; m < 8; m++)
#pragma unroll
        for (int n = 0; n < 4; n++) acc[m][n] = 0ULL;  // (0.f, 0.f)

    const float* Aptr = A + block_row * K;

    for (int k0 = 0; k0 < K; k0 += BK) {
#pragma unroll
        for (int i = 0; i < 2; i++) {
            int r = a_r + i * 64;
            float4 v = *(const float4*)(Aptr + (long long)r * K + k0 + a_c);
            As[(a_c + 0) * ASTRIDE + r] = v.x;
            As[(a_c + 1) * ASTRIDE + r] = v.y;
            As[(a_c + 2) * ASTRIDE + r] = v.z;
            As[(a_c + 3) * ASTRIDE + r] = v.w;
        }
#pragma unroll
        for (int i = 0; i < 2; i++) {
            int r = b_r + i * 8;
            float4 v = *(const float4*)(W + (long long)(k0 + r) * N + block_col + b_c);
            *(float4*)&Bs[r * BN + b_c] = v;
        }
        __syncthreads();

#pragma unroll
        for (int kk = 0; kk < BK; kk++) {
            float4 a0 = *(const float4*)&As[kk * ASTRIDE + ty * 8];
            float4 a1 = *(const float4*)&As[kk * ASTRIDE + ty * 8 + 4];
            float4 b0 = *(const float4*)&Bs[kk * BN + tx * 8];
            float4 b1 = *(const float4*)&Bs[kk * BN + tx * 8 + 4];
            float av[8] = {a0.x, a0.y, a0.z, a0.w, a1.x, a1.y, a1.z, a1.w};
            unsigned long long bp[4] = {pack2(b0.x, b0.y), pack2(b0.z, b0.w),
                                        pack2(b1.x, b1.y), pack2(b1.z, b1.w)};
#pragma unroll
            for (int m = 0; m < 8; m++) {
                unsigned long long ap = pack2(av[m], av[m]);
#pragma unroll
                for (int n = 0; n < 4; n++) ffma2(acc[m][n], ap, bp[n]);
            }
        }
        __syncthreads();
    }

    // epilogue: bias + relu, vectorized float2 stores
#pragma unroll
    for (int m = 0; m < 8; m++) {
        long long row = block_row + ty * 8 + m;
#pragma unroll
        for (int n = 0; n < 4; n++) {
            int col = block_col + tx * 8 + n * 2;
            float xv, yv;
            unpack2(acc[m][n], xv, yv);
            xv += bias[col];
            yv += bias[col + 1];
            if (do_relu) {
                xv = fmaxf(xv, 0.f);
                yv = fmaxf(yv, 0.f);
            }
            *(float2*)&C[row * N + col] = make_float2(xv, yv);
        }
    }
}

// ============================================================================
// Kernel 4: final layer (512 -> 1) + FM combine + sigmoid
//   one warp per row
// ============================================================================
__global__ void final_kernel(const float* __restrict__ W4,
                             const float* __restrict__ b4,
                             float* __restrict__ out) {
    const int warp = (blockIdx.x * blockDim.x + threadIdx.x) >> 5;
    const int lane = threadIdx.x & 31;
    if (warp >= B_SZ) return;
    const float* h = &g_h3[(long long)warp * H3];
    float acc = 0.f;
#pragma unroll
    for (int i = 0; i < H3 / 32; i++) acc = fmaf(h[lane + i * 32], W4[lane + i * 32], acc);
#pragma unroll
    for (int o = 16; o > 0; o >>= 1) acc += __shfl_xor_sync(0xffffffff, acc, o);
    if (lane == 0) {
        float z = acc + b4[0] + g_fm0[warp] + 0.5f * g_S[0];
        out[warp] = 1.f / (1.f + expf(-z));
    }
}

// ============================================================================
extern "C" void kernel_launch(void* const* d_in, const int* in_sizes, int n_in,
                              void* d_out, int out_size) {
    const float* x    = (const float*)d_in[0];
    const float* bias = (const float*)d_in[1];
    const float* fc   = (const float*)d_in[2];
    const float* emb  = (const float*)d_in[3];
    const float* W1   = (const float*)d_in[4];
    const float* b1   = (const float*)d_in[5];
    const float* W2   = (const float*)d_in[6];
    const float* b2   = (const float*)d_in[7];
    const float* W3   = (const float*)d_in[8];
    const float* b3   = (const float*)d_in[9];
    const float* W4   = (const float*)d_in[10];
    const float* b4   = (const float*)d_in[11];
    float* out = (float*)d_out;

    float *embed, *h1, *h2, *h3;
    cudaGetSymbolAddress((void**)&embed, g_embed);
    cudaGetSymbolAddress((void**)&h1, g_h1);
    cudaGetSymbolAddress((void**)&h2, g_h2);
    cudaGetSymbolAddress((void**)&h3, g_h3);

    gather_fm_kernel<<<B_SZ, 128>>>(x, bias, fc, emb);
    reduce_t_kernel<<<1, 1024>>>();
    sgemm_bias_act<<<dim3(H1 / BN, B_SZ / BM), 256>>>(embed, W1, b1, h1, H1, D_IN, 1);
    sgemm_bias_act<<<dim3(H2 / BN, B_SZ / BM), 256>>>(h1, W2, b2, h2, H2, H1, 1);
    sgemm_bias_act<<<dim3(H3 / BN, B_SZ / BM), 256>>>(h2, W3, b3, h3, H3, H2, 1);
    final_kernel<<<(B_SZ * 32) / 256, 256>>>(W4, b4, out);
}

// round 3
// speedup vs baseline: 2.5541x; 2.5541x over previous
#include <cuda_runtime.h>
#include <cuda_bf16.h>
#include <math.h>
#include <stdint.h>

#define B_SZ  16384
#define EMB   128
#define NF    4
#define D_IN  512
#define H1    2048
#define H2    1024
#define H3    512

// ---- scratch (device globals) ----
__device__ __nv_bfloat16 g_ehi[B_SZ * D_IN],  g_elo[B_SZ * D_IN];
__device__ __nv_bfloat16 g_h1hi[B_SZ * H1],   g_h1lo[B_SZ * H1];
__device__ __nv_bfloat16 g_h2hi[B_SZ * H2],   g_h2lo[B_SZ * H2];
__device__ __nv_bfloat16 g_h3hi[B_SZ * H3],   g_h3lo[B_SZ * H3];
__device__ float g_fm0[B_SZ];
__device__ float g_t[B_SZ];
__device__ float g_S[1];
#define WT1_OFF 0
#define WT2_OFF (D_IN * H1)
#define WT3_OFF (D_IN * H1 + H1 * H2)
#define WT_TOTAL (D_IN * H1 + H1 * H2 + H2 * H3)
__device__ __nv_bfloat16 g_wth[WT_TOTAL], g_wtl[WT_TOTAL];

__constant__ int c_offsets[4] = {0, 31360, 38167, 38185};

// ============================ PTX helpers ====================================
__device__ __forceinline__ uint32_t smem_u32(const void* p) {
    uint32_t a;
    asm("{ .reg .u64 t; cvta.to.shared.u64 t, %1; cvt.u32.u64 %0, t; }"
        : "=r"(a) : "l"(p));
    return a;
}
__device__ __forceinline__ void cp_async16(uint32_t s, const void* g) {
    asm volatile("cp.async.cg.shared.global [%0], [%1], 16;" :: "r"(s), "l"(g));
}
#define CP_COMMIT() asm volatile("cp.async.commit_group;" ::: "memory")
#define CP_WAIT(n)  asm volatile("cp.async.wait_group %0;" :: "n"(n) : "memory")

__device__ __forceinline__ void ldsm4(uint32_t* r, uint32_t addr) {
    asm volatile("ldmatrix.sync.aligned.m8n8.x4.shared.b16 {%0,%1,%2,%3}, [%4];"
                 : "=r"(r[0]), "=r"(r[1]), "=r"(r[2]), "=r"(r[3]) : "r"(addr));
}
__device__ __forceinline__ void mma_bf16(float* c, const uint32_t* a, const uint32_t* b) {
    asm volatile(
        "mma.sync.aligned.m16n8k16.row.col.f32.bf16.bf16.f32 "
        "{%0,%1,%2,%3}, {%4,%5,%6,%7}, {%8,%9}, {%0,%1,%2,%3};"
        : "+f"(c[0]), "+f"(c[1]), "+f"(c[2]), "+f"(c[3])
        : "r"(a[0]), "r"(a[1]), "r"(a[2]), "r"(a[3]), "r"(b[0]), "r"(b[1]));
}
// swizzled smem offset for a 16B chunk: row r (64B rows), chunk c (0..3)
__device__ __forceinline__ uint32_t swz(int r, int c) {
    return (uint32_t)(r * 64 + ((c ^ ((r >> 1) & 3)) << 4));
}
__device__ __forceinline__ void split_bf16(float v, __nv_bfloat16& h, __nv_bfloat16& l) {
    h = __float2bfloat16_rn(v);
    l = __float2bfloat16_rn(v - __bfloat162float(h));
}

// ============================================================================
// Kernel 1: embedding gather (-> split bf16) + FM partial terms
// ============================================================================
__global__ void gather_fm_kernel(const float* __restrict__ x,
                                 const float* __restrict__ bias,
                                 const float* __restrict__ fc,
                                 const float* __restrict__ emb) {
    const int row = blockIdx.x;
    const int d = threadIdx.x;  // 0..127
    int idx[NF];
#pragma unroll
    for (int f = 0; f < NF; f++) idx[f] = (int)x[row * NF + f];
    float s = 0.f, ss = 0.f;
#pragma unroll
    for (int f = 0; f < NF; f++) {
        float e = emb[(long long)idx[f] * EMB + d];
        __nv_bfloat16 h, l;
        split_bf16(e, h, l);
        long long o = (long long)row * D_IN + f * EMB + d;
        g_ehi[o] = h;
        g_elo[o] = l;
        s += e;
        ss += e * e;
    }
#pragma unroll
    for (int o = 16; o > 0; o >>= 1) {
        s += __shfl_xor_sync(0xffffffff, s, o);
        ss += __shfl_xor_sync(0xffffffff, ss, o);
    }
    __shared__ float ws[4], wss[4];
    if ((d & 31) == 0) { ws[d >> 5] = s; wss[d >> 5] = ss; }
    __syncthreads();
    if (d == 0) {
        float sa = ws[0] + ws[1] + ws[2] + ws[3];
        float sq = wss[0] + wss[1] + wss[2] + wss[3];
        g_t[row] = sa * sa - sq;
        float lin = 0.f;
#pragma unroll
        for (int f = 0; f < NF; f++) lin += fc[idx[f] + c_offsets[f]];
        g_fm0[row] = bias[0] + lin;
    }
}

// ============================================================================
// Kernel 2: global deterministic reduction of g_t
// ============================================================================
__global__ void reduce_t_kernel() {
    __shared__ float sm[1024];
    const int tid = threadIdx.x;
    float s = 0.f;
    for (int i = tid; i < B_SZ; i += 1024) s += g_t[i];
    sm[tid] = s;
    __syncthreads();
#pragma unroll
    for (int o = 512; o > 0; o >>= 1) {
        if (tid < o) sm[tid] += sm[tid + o];
        __syncthreads();
    }
    if (tid == 0) g_S[0] = sm[0];
}

// ============================================================================
// Kernel 3: weight transpose + bf16 hi/lo split.  W[K,N] -> WT_hi/lo[N,K]
// ============================================================================
__global__ void prep_wt_kernel(const float* __restrict__ W,
                               __nv_bfloat16* __restrict__ Wh,
                               __nv_bfloat16* __restrict__ Wl, int K, int N) {
    __shared__ float t[32][33];
    const int n0 = blockIdx.x * 32, k0 = blockIdx.y * 32;
    const int tx = threadIdx.x, ty = threadIdx.y;  // 32 x 8
#pragma unroll
    for (int i = 0; i < 4; i++)
        t[ty + i * 8][tx] = W[(long long)(k0 + ty + i * 8) * N + n0 + tx];
    __syncthreads();
#pragma unroll
    for (int i = 0; i < 4; i++) {
        int y = ty + i * 8;
        float v = t[tx][y];
        __nv_bfloat16 h, l;
        split_bf16(v, h, l);
        Wh[(long long)(n0 + y) * K + k0 + tx] = h;
        Wl[(long long)(n0 + y) * K + k0 + tx] = l;
    }
}

// ============================================================================
// Kernel 4: bf16x3 HMMA GEMM.  C = relu(A @ WT^T + bias), split-stored.
//   A: hi/lo bf16 [M][K], WT: hi/lo bf16 [N][K].  BM=BN=128, BK=32, 3 stages.
// ============================================================================
#define STAGES 3
#define AHI_O 0
#define ALO_O 8192
#define BHI_O 16384
#define BLO_O 24576
#define STAGE_B 32768
#define SMEM_GEMM (STAGES * STAGE_B)

__global__ __launch_bounds__(256) void gemm_bf16x3(
    const __nv_bfloat16* __restrict__ Ah, const __nv_bfloat16* __restrict__ Al,
    const __nv_bfloat16* __restrict__ Bh, const __nv_bfloat16* __restrict__ Bl,
    const float* __restrict__ bias,
    __nv_bfloat162* __restrict__ Chi, __nv_bfloat162* __restrict__ Clo,
    int N, int K, int do_relu) {
    extern __shared__ char smem[];
    const uint32_t sb = smem_u32(smem);
    const int tid = threadIdx.x;
    const int lane = tid & 31;
    const int warp = tid >> 5;
    const int wm = warp & 3;   // 4 warps along M (32 rows each)
    const int wn = warp >> 2;  // 2 warps along N (64 cols each)
    const long long brow = (long long)blockIdx.y * 128;
    const int bcol = blockIdx.x * 128;

    // ldmatrix lane offsets (stage-relative)
    uint32_t aoff[2][2], boff[2][4];
#pragma unroll
    for (int ks = 0; ks < 2; ks++) {
#pragma unroll
        for (int mi = 0; mi < 2; mi++) {
            int r = wm * 32 + mi * 16 + (lane & 15);
            aoff[ks][mi] = swz(r, 2 * ks + (lane >> 4));
        }
#pragma unroll
        for (int p = 0; p < 4; p++) {
            int r = wn * 64 + p * 16 + ((lane >> 4) << 3) + (lane & 7);
            boff[ks][p] = swz(r, 2 * ks + ((lane >> 3) & 1));
        }
    }

    // cp.async chunk coords: thread handles chunks tid and tid+256 of each array
    const int ch0_r = tid >> 2, ch0_c = tid & 3;
    const int ch1_r = (tid + 256) >> 2, ch1_c = tid & 3;
    const uint32_t so0 = swz(ch0_r, ch0_c), so1 = swz(ch1_r, ch1_c);

    float acc[2][8][4];
#pragma unroll
    for (int mi = 0; mi < 2; mi++)
#pragma unroll
        for (int ni = 0; ni < 8; ni++)
#pragma unroll
            for (int j = 0; j < 4; j++) acc[mi][ni][j] = 0.f;

    const int NIT = K >> 5;

    // loader lambda-ish macro
#define ISSUE(buf, k0)                                                          \
    do {                                                                        \
        uint32_t s_ = sb + (buf) * STAGE_B;                                     \
        const __nv_bfloat16* ga;                                                \
        ga = Ah + (brow + ch0_r) * K + (k0) + ch0_c * 8;                        \
        cp_async16(s_ + AHI_O + so0, ga);                                       \
        ga = Ah + (brow + ch1_r) * K + (k0) + ch1_c * 8;                        \
        cp_async16(s_ + AHI_O + so1, ga);                                       \
        ga = Al + (brow + ch0_r) * K + (k0) + ch0_c * 8;                        \
        cp_async16(s_ + ALO_O + so0, ga);                                       \
        ga = Al + (brow + ch1_r) * K + (k0) + ch1_c * 8;                        \
        cp_async16(s_ + ALO_O + so1, ga);                                       \
        ga = Bh + (long long)(bcol + ch0_r) * K + (k0) + ch0_c * 8;             \
        cp_async16(s_ + BHI_O + so0, ga);                                       \
        ga = Bh + (long long)(bcol + ch1_r) * K + (k0) + ch1_c * 8;             \
        cp_async16(s_ + BHI_O + so1, ga);                                       \
        ga = Bl + (long long)(bcol + ch0_r) * K + (k0) + ch0_c * 8;             \
        cp_async16(s_ + BLO_O + so0, ga);                                       \
        ga = Bl + (long long)(bcol + ch1_r) * K + (k0) + ch1_c * 8;             \
        cp_async16(s_ + BLO_O + so1, ga);                                       \
    } while (0)

    // prologue: stages 0..STAGES-2
    ISSUE(0, 0);
    CP_COMMIT();
    ISSUE(1, 32);
    CP_COMMIT();

    for (int it = 0; it < NIT; it++) {
        CP_WAIT(STAGES - 2);
        __syncthreads();
        if (it + STAGES - 1 < NIT) ISSUE((it + STAGES - 1) % STAGES, (it + STAGES - 1) * 32);
        CP_COMMIT();

        const uint32_t st = sb + (it % STAGES) * STAGE_B;
#pragma unroll
        for (int ks = 0; ks < 2; ks++) {
            uint32_t ah[2][4], al[2][4], bh[8][2], bl[8][2];
#pragma unroll
            for (int mi = 0; mi < 2; mi++) {
                ldsm4(ah[mi], st + AHI_O + aoff[ks][mi]);
                ldsm4(al[mi], st + ALO_O + aoff[ks][mi]);
            }
#pragma unroll
            for (int p = 0; p < 4; p++) {
                uint32_t r4[4];
                ldsm4(r4, st + BHI_O + boff[ks][p]);
                bh[2 * p][0] = r4[0]; bh[2 * p][1] = r4[1];
                bh[2 * p + 1][0] = r4[2]; bh[2 * p + 1][1] = r4[3];
                ldsm4(r4, st + BLO_O + boff[ks][p]);
                bl[2 * p][0] = r4[0]; bl[2 * p][1] = r4[1];
                bl[2 * p + 1][0] = r4[2]; bl[2 * p + 1][1] = r4[3];
            }
#pragma unroll
            for (int mi = 0; mi < 2; mi++)
#pragma unroll
                for (int ni = 0; ni < 8; ni++) {
                    mma_bf16(acc[mi][ni], ah[mi], bh[ni]);
                    mma_bf16(acc[mi][ni], ah[mi], bl[ni]);
                    mma_bf16(acc[mi][ni], al[mi], bh[ni]);
                }
        }
    }

    // ---- epilogue: bias + relu, split to bf16 hi/lo pairs ----
    const int gid = lane >> 2, tc = lane & 3;
#pragma unroll
    for (int ni = 0; ni < 8; ni++) {
        const int col = bcol + wn * 64 + ni * 8 + tc * 2;
        const float b0 = bias[col], b1 = bias[col + 1];
#pragma unroll
        for (int mi = 0; mi < 2; mi++) {
            long long r0 = brow + wm * 32 + mi * 16 + gid;
            float v0 = acc[mi][ni][0] + b0, v1 = acc[mi][ni][1] + b1;
            float v2 = acc[mi][ni][2] + b0, v3 = acc[mi][ni][3] + b1;
            if (do_relu) {
                v0 = fmaxf(v0, 0.f); v1 = fmaxf(v1, 0.f);
                v2 = fmaxf(v2, 0.f); v3 = fmaxf(v3, 0.f);
            }
            __nv_bfloat16 h0, l0, h1, l1;
            split_bf16(v0, h0, l0); split_bf16(v1, h1, l1);
            long long o0 = (r0 * N + col) >> 1;
            Chi[o0] = __nv_bfloat162(h0, h1);
            Clo[o0] = __nv_bfloat162(l0, l1);
            split_bf16(v2, h0, l0); split_bf16(v3, h1, l1);
            long long o1 = ((r0 + 8) * N + col) >> 1;
            Chi[o1] = __nv_bfloat162(h0, h1);
            Clo[o1] = __nv_bfloat162(l0, l1);
        }
    }
#undef ISSUE
}

// ============================================================================
// Kernel 5: final layer (512 -> 1) + FM combine + sigmoid
// ============================================================================
__global__ void final_kernel(const float* __restrict__ W4,
                             const float* __restrict__ b4,
                             float* __restrict__ out) {
    const int warp = (blockIdx.x * blockDim.x + threadIdx.x) >> 5;
    const int lane = threadIdx.x & 31;
    if (warp >= B_SZ) return;
    const __nv_bfloat16* hh = &g_h3hi[(long long)warp * H3];
    const __nv_bfloat16* hl = &g_h3lo[(long long)warp * H3];
    float acc = 0.f;
#pragma unroll
    for (int i = 0; i < H3 / 32; i++) {
        int j = lane + i * 32;
        float h = __bfloat162float(hh[j]) + __bfloat162float(hl[j]);
        acc = fmaf(h, W4[j], acc);
    }
#pragma unroll
    for (int o = 16; o > 0; o >>= 1) acc += __shfl_xor_sync(0xffffffff, acc, o);
    if (lane == 0) {
        float z = acc + b4[0] + g_fm0[warp] + 0.5f * g_S[0];
        out[warp] = 1.f / (1.f + expf(-z));
    }
}

// ============================================================================
extern "C" void kernel_launch(void* const* d_in, const int* in_sizes, int n_in,
                              void* d_out, int out_size) {
    const float* x    = (const float*)d_in[0];
    const float* bias = (const float*)d_in[1];
    const float* fc   = (const float*)d_in[2];
    const float* emb  = (const float*)d_in[3];
    const float* W1   = (const float*)d_in[4];
    const float* b1   = (const float*)d_in[5];
    const float* W2   = (const float*)d_in[6];
    const float* b2   = (const float*)d_in[7];
    const float* W3   = (const float*)d_in[8];
    const float* b3   = (const float*)d_in[9];
    const float* W4   = (const float*)d_in[10];
    const float* b4   = (const float*)d_in[11];
    float* out = (float*)d_out;

    __nv_bfloat16 *ehi, *elo, *h1hi, *h1lo, *h2hi, *h2lo, *h3hi, *h3lo, *wth, *wtl;
    cudaGetSymbolAddress((void**)&ehi, g_ehi);
    cudaGetSymbolAddress((void**)&elo, g_elo);
    cudaGetSymbolAddress((void**)&h1hi, g_h1hi);
    cudaGetSymbolAddress((void**)&h1lo, g_h1lo);
    cudaGetSymbolAddress((void**)&h2hi, g_h2hi);
    cudaGetSymbolAddress((void**)&h2lo, g_h2lo);
    cudaGetSymbolAddress((void**)&h3hi, g_h3hi);
    cudaGetSymbolAddress((void**)&h3lo, g_h3lo);
    cudaGetSymbolAddress((void**)&wth, g_wth);
    cudaGetSymbolAddress((void**)&wtl, g_wtl);

    cudaFuncSetAttribute(gemm_bf16x3, cudaFuncAttributeMaxDynamicSharedMemorySize,
                         SMEM_GEMM);

    prep_wt_kernel<<<dim3(H1 / 32, D_IN / 32), dim3(32, 8)>>>(W1, wth + WT1_OFF,
                                                              wtl + WT1_OFF, D_IN, H1);
    prep_wt_kernel<<<dim3(H2 / 32, H1 / 32), dim3(32, 8)>>>(W2, wth + WT2_OFF,
                                                            wtl + WT2_OFF, H1, H2);
    prep_wt_kernel<<<dim3(H3 / 32, H2 / 32), dim3(32, 8)>>>(W3, wth + WT3_OFF,
                                                            wtl + WT3_OFF, H2, H3);

    gather_fm_kernel<<<B_SZ, 128>>>(x, bias, fc, emb);
    reduce_t_kernel<<<1, 1024>>>();

    gemm_bf16x3<<<dim3(H1 / 128, B_SZ / 128), 256, SMEM_GEMM>>>(
        ehi, elo, wth + WT1_OFF, wtl + WT1_OFF, b1,
        (__nv_bfloat162*)h1hi, (__nv_bfloat162*)h1lo, H1, D_IN, 1);
    gemm_bf16x3<<<dim3(H2 / 128, B_SZ / 128), 256, SMEM_GEMM>>>(
        h1hi, h1lo, wth + WT2_OFF, wtl + WT2_OFF, b2,
        (__nv_bfloat162*)h2hi, (__nv_bfloat162*)h2lo, H2, H1, 1);
    gemm_bf16x3<<<dim3(H3 / 128, B_SZ / 128), 256, SMEM_GEMM>>>(
        h2hi, h2lo, wth + WT3_OFF, wtl + WT3_OFF, b3,
        (__nv_bfloat162*)h3hi, (__nv_bfloat162*)h3lo, H3, H2, 1);

    final_kernel<<<(B_SZ * 32) / 256, 256>>>(W4, b4, out);
}

// round 4
// speedup vs baseline: 7.4754x; 2.9269x over previous
#include <cuda_runtime.h>
#include <cuda_bf16.h>
#include <math.h>
#include <stdint.h>

#define B_SZ  16384
#define EMB   128
#define NF    4
#define D_IN  512
#define H1    2048
#define H2    1024
#define H3    512

// ---- scratch (device globals) ----
__device__ __nv_bfloat16 g_e[B_SZ * D_IN];
__device__ __nv_bfloat16 g_h1[B_SZ * H1];
__device__ __nv_bfloat16 g_h2[B_SZ * H2];
__device__ __nv_bfloat16 g_h3[B_SZ * H3];
__device__ float g_fm0[B_SZ];
__device__ float g_t[B_SZ];
__device__ float g_S[1];
#define WT1_OFF 0
#define WT2_OFF (D_IN * H1)
#define WT3_OFF (D_IN * H1 + H1 * H2)
#define WT_TOTAL (D_IN * H1 + H1 * H2 + H2 * H3)
__device__ __nv_bfloat16 g_wt[WT_TOTAL];

__constant__ int c_offsets[4] = {0, 31360, 38167, 38185};

// ============================ PTX helpers ====================================
__device__ __forceinline__ uint32_t smem_u32(const void* p) {
    uint32_t a;
    asm("{ .reg .u64 t; cvta.to.shared.u64 t, %1; cvt.u32.u64 %0, t; }"
        : "=r"(a) : "l"(p));
    return a;
}
__device__ __forceinline__ void cp_async16(uint32_t s, const void* g) {
    asm volatile("cp.async.cg.shared.global [%0], [%1], 16;" :: "r"(s), "l"(g));
}
#define CP_COMMIT() asm volatile("cp.async.commit_group;" ::: "memory")
#define CP_WAIT(n)  asm volatile("cp.async.wait_group %0;" :: "n"(n) : "memory")

__device__ __forceinline__ void ldsm4(uint32_t* r, uint32_t addr) {
    asm volatile("ldmatrix.sync.aligned.m8n8.x4.shared.b16 {%0,%1,%2,%3}, [%4];"
                 : "=r"(r[0]), "=r"(r[1]), "=r"(r[2]), "=r"(r[3]) : "r"(addr));
}
__device__ __forceinline__ void mma_bf16(float* c, const uint32_t* a, const uint32_t* b) {
    asm volatile(
        "mma.sync.aligned.m16n8k16.row.col.f32.bf16.bf16.f32 "
        "{%0,%1,%2,%3}, {%4,%5,%6,%7}, {%8,%9}, {%0,%1,%2,%3};"
        : "+f"(c[0]), "+f"(c[1]), "+f"(c[2]), "+f"(c[3])
        : "r"(a[0]), "r"(a[1]), "r"(a[2]), "r"(a[3]), "r"(b[0]), "r"(b[1]));
}
// swizzled smem offset for a 16B chunk: row r (64B rows), chunk c (0..3)
__device__ __forceinline__ uint32_t swz(int r, int c) {
    return (uint32_t)(r * 64 + ((c ^ ((r >> 1) & 3)) << 4));
}

// ============================================================================
// Kernel 1: embedding gather (-> bf16) + FM partial terms (fp32, exact path)
// ============================================================================
__global__ void gather_fm_kernel(const float* __restrict__ x,
                                 const float* __restrict__ bias,
                                 const float* __restrict__ fc,
                                 const float* __restrict__ emb) {
    const int row = blockIdx.x;
    const int d = threadIdx.x;  // 0..127
    int idx[NF];
#pragma unroll
    for (int f = 0; f < NF; f++) idx[f] = (int)x[row * NF + f];
    float s = 0.f, ss = 0.f;
#pragma unroll
    for (int f = 0; f < NF; f++) {
        float e = emb[(long long)idx[f] * EMB + d];
        g_e[(long long)row * D_IN + f * EMB + d] = __float2bfloat16_rn(e);
        s += e;
        ss += e * e;
    }
#pragma unroll
    for (int o = 16; o > 0; o >>= 1) {
        s += __shfl_xor_sync(0xffffffff, s, o);
        ss += __shfl_xor_sync(0xffffffff, ss, o);
    }
    __shared__ float ws[4], wss[4];
    if ((d & 31) == 0) { ws[d >> 5] = s; wss[d >> 5] = ss; }
    __syncthreads();
    if (d == 0) {
        float sa = ws[0] + ws[1] + ws[2] + ws[3];
        float sq = wss[0] + wss[1] + wss[2] + wss[3];
        g_t[row] = sa * sa - sq;
        float lin = 0.f;
#pragma unroll
        for (int f = 0; f < NF; f++) lin += fc[idx[f] + c_offsets[f]];
        g_fm0[row] = bias[0] + lin;
    }
}

// ============================================================================
// Kernel 2: global deterministic reduction of g_t
// ============================================================================
__global__ void reduce_t_kernel() {
    __shared__ float sm[1024];
    const int tid = threadIdx.x;
    float s = 0.f;
    for (int i = tid; i < B_SZ; i += 1024) s += g_t[i];
    sm[tid] = s;
    __syncthreads();
#pragma unroll
    for (int o = 512; o > 0; o >>= 1) {
        if (tid < o) sm[tid] += sm[tid + o];
        __syncthreads();
    }
    if (tid == 0) g_S[0] = sm[0];
}

// ============================================================================
// Kernel 3: weight transpose + bf16 convert.  W[K,N] -> WT[N,K] bf16
// ============================================================================
__global__ void prep_wt_kernel(const float* __restrict__ W,
                               __nv_bfloat16* __restrict__ Wt, int K, int N) {
    __shared__ float t[32][33];
    const int n0 = blockIdx.x * 32, k0 = blockIdx.y * 32;
    const int tx = threadIdx.x, ty = threadIdx.y;  // 32 x 8
#pragma unroll
    for (int i = 0; i < 4; i++)
        t[ty + i * 8][tx] = W[(long long)(k0 + ty + i * 8) * N + n0 + tx];
    __syncthreads();
#pragma unroll
    for (int i = 0; i < 4; i++) {
        int y = ty + i * 8;
        Wt[(long long)(n0 + y) * K + k0 + tx] = __float2bfloat16_rn(t[tx][y]);
    }
}

// ============================================================================
// Kernel 4: bf16 HMMA GEMM.  C = relu(A @ WT^T + bias)  (bf16 out)
//   A: bf16 [M][K], WT: bf16 [N][K].  BM=BN=128, BK=32, 4-stage cp.async.
// ============================================================================
#define STAGES 4
#define A_O 0
#define B_O 8192
#define STAGE_B 16384
#define SMEM_GEMM (STAGES * STAGE_B)   // 64 KB

__global__ __launch_bounds__(256, 2) void gemm_bf16(
    const __nv_bfloat16* __restrict__ A, const __nv_bfloat16* __restrict__ Bw,
    const float* __restrict__ bias, __nv_bfloat162* __restrict__ C,
    int N, int K, int do_relu) {
    extern __shared__ char smem[];
    const uint32_t sb = smem_u32(smem);
    const int tid = threadIdx.x;
    const int lane = tid & 31;
    const int warp = tid >> 5;
    const int wm = warp & 3;   // 4 warps along M (32 rows each)
    const int wn = warp >> 2;  // 2 warps along N (64 cols each)
    const long long brow = (long long)blockIdx.y * 128;
    const int bcol = blockIdx.x * 128;

    // ldmatrix lane offsets (stage-relative), ks = k16 index within BK=32
    uint32_t aoff[2][2], boff[2][4];
#pragma unroll
    for (int ks = 0; ks < 2; ks++) {
#pragma unroll
        for (int mi = 0; mi < 2; mi++) {
            int r = wm * 32 + mi * 16 + (lane & 15);
            aoff[ks][mi] = swz(r, 2 * ks + (lane >> 4));
        }
#pragma unroll
        for (int p = 0; p < 4; p++) {
            int r = wn * 64 + p * 16 + ((lane >> 4) << 3) + (lane & 7);
            boff[ks][p] = swz(r, 2 * ks + ((lane >> 3) & 1));
        }
    }

    // cp.async chunk coords: thread handles chunks tid and tid+256 per array
    const int ch0_r = tid >> 2, ch0_c = tid & 3;
    const int ch1_r = (tid + 256) >> 2, ch1_c = tid & 3;
    const uint32_t so0 = swz(ch0_r, ch0_c), so1 = swz(ch1_r, ch1_c);

    float acc[2][8][4];
#pragma unroll
    for (int mi = 0; mi < 2; mi++)
#pragma unroll
        for (int ni = 0; ni < 8; ni++)
#pragma unroll
            for (int j = 0; j < 4; j++) acc[mi][ni][j] = 0.f;

    const int NIT = K >> 5;

#define ISSUE(buf, k0)                                                          \
    do {                                                                        \
        uint32_t s_ = sb + (buf) * STAGE_B;                                     \
        cp_async16(s_ + A_O + so0, A + (brow + ch0_r) * K + (k0) + ch0_c * 8);  \
        cp_async16(s_ + A_O + so1, A + (brow + ch1_r) * K + (k0) + ch1_c * 8);  \
        cp_async16(s_ + B_O + so0,                                              \
                   Bw + (long long)(bcol + ch0_r) * K + (k0) + ch0_c * 8);      \
        cp_async16(s_ + B_O + so1,                                              \
                   Bw + (long long)(bcol + ch1_r) * K + (k0) + ch1_c * 8);      \
    } while (0)

    ISSUE(0, 0);
    CP_COMMIT();
    ISSUE(1, 32);
    CP_COMMIT();
    ISSUE(2, 64);
    CP_COMMIT();

    for (int it = 0; it < NIT; it++) {
        CP_WAIT(STAGES - 2);
        __syncthreads();
        if (it + STAGES - 1 < NIT) ISSUE((it + STAGES - 1) & 3, (it + STAGES - 1) * 32);
        CP_COMMIT();

        const uint32_t st = sb + (it & 3) * STAGE_B;
#pragma unroll
        for (int ks = 0; ks < 2; ks++) {
            uint32_t a[2][4], b[8][2];
#pragma unroll
            for (int mi = 0; mi < 2; mi++) ldsm4(a[mi], st + A_O + aoff[ks][mi]);
#pragma unroll
            for (int p = 0; p < 4; p++) {
                uint32_t r4[4];
                ldsm4(r4, st + B_O + boff[ks][p]);
                b[2 * p][0] = r4[0]; b[2 * p][1] = r4[1];
                b[2 * p + 1][0] = r4[2]; b[2 * p + 1][1] = r4[3];
            }
#pragma unroll
            for (int mi = 0; mi < 2; mi++)
#pragma unroll
                for (int ni = 0; ni < 8; ni++) mma_bf16(acc[mi][ni], a[mi], b[ni]);
        }
    }

    // ---- epilogue: bias + relu -> bf16 ----
    const int gid = lane >> 2, tc = lane & 3;
#pragma unroll
    for (int ni = 0; ni < 8; ni++) {
        const int col = bcol + wn * 64 + ni * 8 + tc * 2;
        const float b0 = bias[col], b1 = bias[col + 1];
#pragma unroll
        for (int mi = 0; mi < 2; mi++) {
            long long r0 = brow + wm * 32 + mi * 16 + gid;
            float v0 = acc[mi][ni][0] + b0, v1 = acc[mi][ni][1] + b1;
            float v2 = acc[mi][ni][2] + b0, v3 = acc[mi][ni][3] + b1;
            if (do_relu) {
                v0 = fmaxf(v0, 0.f); v1 = fmaxf(v1, 0.f);
                v2 = fmaxf(v2, 0.f); v3 = fmaxf(v3, 0.f);
            }
            C[(r0 * N + col) >> 1] =
                __nv_bfloat162(__float2bfloat16_rn(v0), __float2bfloat16_rn(v1));
            C[((r0 + 8) * N + col) >> 1] =
                __nv_bfloat162(__float2bfloat16_rn(v2), __float2bfloat16_rn(v3));
        }
    }
#undef ISSUE
}

// ============================================================================
// Kernel 5: final layer (512 -> 1) + FM combine + sigmoid
// ============================================================================
__global__ void final_kernel(const float* __restrict__ W4,
                             const float* __restrict__ b4,
                             float* __restrict__ out) {
    const int warp = (blockIdx.x * blockDim.x + threadIdx.x) >> 5;
    const int lane = threadIdx.x & 31;
    if (warp >= B_SZ) return;
    const __nv_bfloat16* h = &g_h3[(long long)warp * H3];
    float acc = 0.f;
#pragma unroll
    for (int i = 0; i < H3 / 32; i++) {
        int j = lane + i * 32;
        acc = fmaf(__bfloat162float(h[j]), W4[j], acc);
    }
#pragma unroll
    for (int o = 16; o > 0; o >>= 1) acc += __shfl_xor_sync(0xffffffff, acc, o);
    if (lane == 0) {
        float z = acc + b4[0] + g_fm0[warp] + 0.5f * g_S[0];
        out[warp] = 1.f / (1.f + expf(-z));
    }
}

// ============================================================================
extern "C" void kernel_launch(void* const* d_in, const int* in_sizes, int n_in,
                              void* d_out, int out_size) {
    const float* x    = (const float*)d_in[0];
    const float* bias = (const float*)d_in[1];
    const float* fc   = (const float*)d_in[2];
    const float* emb  = (const float*)d_in[3];
    const float* W1   = (const float*)d_in[4];
    const float* b1   = (const float*)d_in[5];
    const float* W2   = (const float*)d_in[6];
    const float* b2   = (const float*)d_in[7];
    const float* W3   = (const float*)d_in[8];
    const float* b3   = (const float*)d_in[9];
    const float* W4   = (const float*)d_in[10];
    const float* b4   = (const float*)d_in[11];
    float* out = (float*)d_out;

    __nv_bfloat16 *e, *h1, *h2, *h3, *wt;
    cudaGetSymbolAddress((void**)&e, g_e);
    cudaGetSymbolAddress((void**)&h1, g_h1);
    cudaGetSymbolAddress((void**)&h2, g_h2);
    cudaGetSymbolAddress((void**)&h3, g_h3);
    cudaGetSymbolAddress((void**)&wt, g_wt);

    cudaFuncSetAttribute(gemm_bf16, cudaFuncAttributeMaxDynamicSharedMemorySize,
                         SMEM_GEMM);

    prep_wt_kernel<<<dim3(H1 / 32, D_IN / 32), dim3(32, 8)>>>(W1, wt + WT1_OFF, D_IN, H1);
    prep_wt_kernel<<<dim3(H2 / 32, H1 / 32), dim3(32, 8)>>>(W2, wt + WT2_OFF, H1, H2);
    prep_wt_kernel<<<dim3(H3 / 32, H2 / 32), dim3(32, 8)>>>(W3, wt + WT3_OFF, H2, H3);

    gather_fm_kernel<<<B_SZ, 128>>>(x, bias, fc, emb);
    reduce_t_kernel<<<1, 1024>>>();

    gemm_bf16<<<dim3(H1 / 128, B_SZ / 128), 256, SMEM_GEMM>>>(
        e, wt + WT1_OFF, b1, (__nv_bfloat162*)h1, H1, D_IN, 1);
    gemm_bf16<<<dim3(H2 / 128, B_SZ / 128), 256, SMEM_GEMM>>>(
        h1, wt + WT2_OFF, b2, (__nv_bfloat162*)h2, H2, H1, 1);
    gemm_bf16<<<dim3(H3 / 128, B_SZ / 128), 256, SMEM_GEMM>>>(
        h2, wt + WT3_OFF, b3, (__nv_bfloat162*)h3, H3, H2, 1);

    final_kernel<<<(B_SZ * 32) / 256, 256>>>(W4, b4, out);
}